// round 15
// baseline (speedup 1.0000x reference)
#include <cuda_runtime.h>
#include <cstdint>
#include <cstring>

// Problem dims
#define BDIM 64
#define TDIM 512
#define KDIM 1024   // IN_DIM
#define HDIM 1024   // HID
#define MTOT (BDIM * TDIM)   // 32768 rows of the GEMM

// exp(-1/20) rounded to nearest fp32
#define ALPHA 0.9512294245007140f

// Scratch for I = x @ W^T + b   (128 MB, static device allocation — guard-safe)
__device__ float g_I[(size_t)MTOT * HDIM];

typedef unsigned long long u64;

// packed fma: both lanes round exactly like scalar fma.rn.f32
__device__ __forceinline__ void fma2(u64& d, u64 a, u64 b) {
    asm("fma.rn.f32x2 %0, %1, %2, %0;" : "+l"(d) : "l"(a), "l"(b));
}
__device__ __forceinline__ u64 pack2(float lo, float hi) {
    u64 r;
    asm("mov.b64 %0, {%1, %2};" : "=l"(r) : "f"(lo), "f"(hi));
    return r;
}

// ---------------------------------------------------------------------------
// SGEMM (NT), Eigen-ordered accumulation (numerics VERIFIED R7/R9-R14):
//   per output: in-order FMA chain k ascending, fold (fadd) at k=1016,
//   fadd of 8-wide tail chain, fadd bias.
// FFMA2 v6 — at the structural floor (64 FFMA2 x rt3 = 192 cyc/k-step/SMSP).
// Unchanged from R13/R14 except the cRowBase offset (pure indexing).
// ---------------------------------------------------------------------------
constexpr int BM = 128, BN = 128, BK = 8, TM = 8, TN = 8;
constexpr int NKB = KDIM / BK;       // 128 tiles; tiles 0..126 = k<1016

__global__ __launch_bounds__(256, 1) void sgemm_nt_bias_eigen_f32x2(
    const float* __restrict__ A,      // [MTOT, KDIM] row-major
    const float* __restrict__ W,      // [HDIM, KDIM] row-major
    const float* __restrict__ bias,   // [HDIM]
    int cRowBase)                     // M-tile offset for batch-group split
{
    __shared__ float As[2][BK][BM];   // As[buf][k][m]
    __shared__ float Bs[2][BK][BN];   // Bs[buf][k][n]

    const int cRow = cRowBase + blockIdx.y;
    const int cCol = blockIdx.x;
    const int tid  = threadIdx.x;

    const int threadRow = (tid / 16) * TM;   // 0..120 (warp-broadcast A)
    const int colLo     = (tid % 16) * 4;    // cols colLo..colLo+3
    const int colHi     = colLo + 64;        // cols colHi..colHi+3

    // staging: one float4 per matrix per thread per k-tile
    const int innerRow = tid / 2;          // 0..127 (m or n index)
    const int innerCol = (tid % 2) * 4;    // k offset 0 or 4

    const float* Aptr = A + (size_t)cRow * BM * KDIM + (size_t)innerRow * KDIM + innerCol;
    const float* Wptr = W + (size_t)cCol * BN * KDIM + (size_t)innerRow * KDIM + innerCol;

    u64 acc2[TM * TN / 2];                 // pairs along N: 32 u64 = 64 regs
    #pragma unroll
    for (int i = 0; i < TM * TN / 2; i++) acc2[i] = 0ull;

    // ---- stage tile 0 ----
    float4 ra = *reinterpret_cast<const float4*>(Aptr);
    float4 rb = *reinterpret_cast<const float4*>(Wptr);
    {
        const float av[4] = {ra.x, ra.y, ra.z, ra.w};
        const float bv[4] = {rb.x, rb.y, rb.z, rb.w};
        #pragma unroll
        for (int j = 0; j < 4; j++) {
            As[0][innerCol + j][innerRow] = av[j];
            Bs[0][innerCol + j][innerRow] = bv[j];
        }
    }
    __syncthreads();

    // ---- compute one k-tile from buffer `buf` (k ascending, FFMA2 chains) ----
    auto compute_tile = [&](int buf) {
        #pragma unroll
        for (int k = 0; k < BK; k++) {
            float4 a0 = *reinterpret_cast<const float4*>(&As[buf][k][threadRow + 0]);
            float4 a1 = *reinterpret_cast<const float4*>(&As[buf][k][threadRow + 4]);
            float4 b0 = *reinterpret_cast<const float4*>(&Bs[buf][k][colLo]);  // conflict-free
            float4 b1 = *reinterpret_cast<const float4*>(&Bs[buf][k][colHi]);

            u64 n[4];
            memcpy(&n[0], &b0.x, 8); memcpy(&n[1], &b0.z, 8);
            memcpy(&n[2], &b1.x, 8); memcpy(&n[3], &b1.z, 8);

            const float mv[TM] = {a0.x, a0.y, a0.z, a0.w, a1.x, a1.y, a1.z, a1.w};
            u64 m2[TM];
            #pragma unroll
            for (int i = 0; i < TM; i++) m2[i] = pack2(mv[i], mv[i]);  // ALU pipe

            #pragma unroll
            for (int p = 0; p < 4; p++) {
                #pragma unroll
                for (int i = 0; i < TM; i++) {
                    fma2(acc2[i * 4 + p], m2[i], n[p]);
                }
            }
        }
    };

    // ---- main loop: tiles 0..126  (k = 0..1015, the Eigen kc=1016 panel) ----
    for (int kb = 0; kb < NKB - 1; kb++) {
        const int cur = kb & 1, nxt = cur ^ 1;

        ra = *reinterpret_cast<const float4*>(Aptr + (size_t)(kb + 1) * BK);
        rb = *reinterpret_cast<const float4*>(Wptr + (size_t)(kb + 1) * BK);

        compute_tile(cur);

        const float av[4] = {ra.x, ra.y, ra.z, ra.w};
        const float bv[4] = {rb.x, rb.y, rb.z, rb.w};
        #pragma unroll
        for (int j = 0; j < 4; j++) {
            As[nxt][innerCol + j][innerRow] = av[j];
            Bs[nxt][innerCol + j][innerRow] = bv[j];
        }
        __syncthreads();
    }

    // ---- Eigen fold at k=1016: sum <- chain  (bitwise == fadd(0, chain)) ----
    u64 sum2[TM * TN / 2];
    #pragma unroll
    for (int i = 0; i < TM * TN / 2; i++) { sum2[i] = acc2[i]; acc2[i] = 0ull; }

    // ---- tail tile 127 (k = 1016..1023) ----
    compute_tile((NKB - 1) & 1);

    // ---- epilogue: o = fadd(fadd(sum, tail), bias)  (scalar, exactly R7) ----
    #pragma unroll
    for (int i = 0; i < TM; i++) {
        const size_t row = (size_t)cRow * BM + threadRow + i;
        #pragma unroll
        for (int half = 0; half < 2; half++) {
            const int col = cCol * BN + (half == 0 ? colLo : colHi);
            float4 bv = *reinterpret_cast<const float4*>(&bias[col]);
            float s[4], t[4];
            memcpy(&s[0], &sum2[i * 4 + half * 2 + 0], 8);
            memcpy(&s[2], &sum2[i * 4 + half * 2 + 1], 8);
            memcpy(&t[0], &acc2[i * 4 + half * 2 + 0], 8);
            memcpy(&t[2], &acc2[i * 4 + half * 2 + 1], 8);
            float4 o;
            o.x = __fadd_rn(__fadd_rn(s[0], t[0]), bv.x);
            o.y = __fadd_rn(__fadd_rn(s[1], t[1]), bv.y);
            o.z = __fadd_rn(__fadd_rn(s[2], t[2]), bv.z);
            o.w = __fadd_rn(__fadd_rn(s[3], t[3]), bv.w);
            *reinterpret_cast<float4*>(&g_I[row * HDIM + col]) = o;
        }
    }
}

// ---------------------------------------------------------------------------
// LIF scan v2 (R14, 49.8 us): chunked prefetch, MLP=16. bBase = batch offset
// for the group split; per-(b,h) arithmetic identical.
// ---------------------------------------------------------------------------
constexpr int SCHUNK = 16;

__global__ __launch_bounds__(256) void lif_scan(
    float* __restrict__ spikes,      // [B,T,H]
    float* __restrict__ mem_final,   // [B,H]
    int bBase)
{
    const int lidx = blockIdx.x * blockDim.x + threadIdx.x;  // over nb*H
    const int b = bBase + lidx / HDIM;
    const int h = lidx % HDIM;
    const int idx = b * HDIM + h;

    const float* Ip = g_I + (size_t)b * TDIM * HDIM + h;
    float* Sp = spikes + (size_t)b * TDIM * HDIM + h;

    float mem = 0.0f;
    for (int tb = 0; tb < TDIM; tb += SCHUNK) {
        float v[SCHUNK];
        #pragma unroll
        for (int j = 0; j < SCHUNK; j++)
            v[j] = Ip[(size_t)(tb + j) * HDIM];          // independent LDGs

        #pragma unroll
        for (int j = 0; j < SCHUNK; j++) {
            mem = __fadd_rn(__fmul_rn(ALPHA, mem), v[j]);
            const bool fire = (mem >= 1.0f);
            Sp[(size_t)(tb + j) * HDIM] = fire ? 1.0f : 0.0f;
            mem = fire ? 0.0f : mem;
        }
    }
    mem_final[idx] = mem;
}

// ---------------------------------------------------------------------------
// Overlap resources: a non-blocking side stream + fork/join events.
// Created once at static init (host/driver objects only — no device memory).
// NonBlocking is REQUIRED: a default (blocking) stream would implicitly
// serialize against the legacy capture stream and kill the overlap.
// ---------------------------------------------------------------------------
static cudaStream_t g_s1;
static cudaEvent_t  g_evFork, g_evJoin;
static struct StreamInit {
    StreamInit() {
        cudaStreamCreateWithFlags(&g_s1, cudaStreamNonBlocking);
        cudaEventCreateWithFlags(&g_evFork, cudaEventDisableTiming);
        cudaEventCreateWithFlags(&g_evJoin, cudaEventDisableTiming);
    }
} g_streamInit;

// Batch-group split: group0 = 37 batches -> 148 M-tiles -> 1184 CTAs = 8.0
// exact waves; group1 = 27 batches -> 108 M-tiles -> 864 CTAs = 6 waves.
constexpr int NB0     = 37;            // batches in group 0
constexpr int TILES0  = NB0 * 4;       // 148 M-tiles
constexpr int TILES1  = (BDIM - NB0) * 4;  // 108 M-tiles

extern "C" void kernel_launch(void* const* d_in, const int* in_sizes, int n_in,
                              void* d_out, int out_size)
{
    const float* x  = (const float*)d_in[0];   // [B,T,IN]
    const float* W  = (const float*)d_in[1];   // [HID,IN]
    const float* b  = (const float*)d_in[2];   // [HID]

    float* out      = (float*)d_out;
    float* spikes   = out;                                   // B*T*H floats
    float* mem_fin  = out + (size_t)MTOT * HDIM;             // B*H floats

    // GEMM group 0 (batches 0..36) on the main (capture) stream
    sgemm_nt_bias_eigen_f32x2<<<dim3(HDIM / BN, TILES0), 256>>>(x, W, b, 0);
    cudaEventRecord(g_evFork, 0);

    // GEMM group 1 (batches 37..63) continues on the main stream
    sgemm_nt_bias_eigen_f32x2<<<dim3(HDIM / BN, TILES1), 256>>>(x, W, b, TILES0);

    // scan group 0 overlaps GEMM group 1 on the side stream
    cudaStreamWaitEvent(g_s1, g_evFork, 0);
    lif_scan<<<NB0 * HDIM / 256, 256, 0, g_s1>>>(spikes, mem_fin, 0);
    cudaEventRecord(g_evJoin, g_s1);

    // scan group 1 after GEMM group 1 (main stream order)
    lif_scan<<<(BDIM - NB0) * HDIM / 256, 256>>>(spikes, mem_fin, NB0);

    // join the side stream back into the main stream
    cudaStreamWaitEvent(0, g_evJoin, 0);
}

// round 16
// speedup vs baseline: 1.0270x; 1.0270x over previous
#include <cuda_runtime.h>
#include <cstdint>
#include <cstring>

// Problem dims
#define BDIM 64
#define TDIM 512
#define KDIM 1024   // IN_DIM
#define HDIM 1024   // HID
#define MTOT (BDIM * TDIM)   // 32768 rows of the GEMM

// exp(-1/20) rounded to nearest fp32
#define ALPHA 0.9512294245007140f

// Scratch for I = x @ W^T + b   (128 MB, static device allocation — guard-safe)
__device__ float g_I[(size_t)MTOT * HDIM];

// Per-batch readiness counters (32 GEMM CTAs per batch). Zeroed each call.
__device__ unsigned int g_ready[BDIM];

typedef unsigned long long u64;

// packed fma: both lanes round exactly like scalar fma.rn.f32
__device__ __forceinline__ void fma2(u64& d, u64 a, u64 b) {
    asm("fma.rn.f32x2 %0, %1, %2, %0;" : "+l"(d) : "l"(a), "l"(b));
}
__device__ __forceinline__ u64 pack2(float lo, float hi) {
    u64 r;
    asm("mov.b64 %0, {%1, %2};" : "=l"(r) : "f"(lo), "f"(hi));
    return r;
}

// ---------------------------------------------------------------------------
// SGEMM (NT), Eigen-ordered accumulation (numerics VERIFIED R7/R9-R15):
//   per output: in-order FMA chain k ascending, fold (fadd) at k=1016,
//   fadd of 8-wide tail chain, fadd bias.
// FFMA2 v6 — at the structural floor (64 FFMA2 x rt3 = 192 cyc/k-step/SMSP).
// Single 2048-CTA launch (no split, no drain bubble). Epilogue additionally
// releases a per-batch ready counter (fence + atomicAdd; no fp changes).
// ---------------------------------------------------------------------------
constexpr int BM = 128, BN = 128, BK = 8, TM = 8, TN = 8;
constexpr int NKB = KDIM / BK;       // 128 tiles; tiles 0..126 = k<1016

__global__ __launch_bounds__(256, 1) void sgemm_nt_bias_eigen_f32x2(
    const float* __restrict__ A,      // [MTOT, KDIM] row-major
    const float* __restrict__ W,      // [HDIM, KDIM] row-major
    const float* __restrict__ bias)   // [HDIM]
{
    __shared__ float As[2][BK][BM];   // As[buf][k][m]
    __shared__ float Bs[2][BK][BN];   // Bs[buf][k][n]

    const int cRow = blockIdx.y;
    const int cCol = blockIdx.x;
    const int tid  = threadIdx.x;

    const int threadRow = (tid / 16) * TM;   // 0..120 (warp-broadcast A)
    const int colLo     = (tid % 16) * 4;    // cols colLo..colLo+3
    const int colHi     = colLo + 64;        // cols colHi..colHi+3

    // staging: one float4 per matrix per thread per k-tile
    const int innerRow = tid / 2;          // 0..127 (m or n index)
    const int innerCol = (tid % 2) * 4;    // k offset 0 or 4

    const float* Aptr = A + (size_t)cRow * BM * KDIM + (size_t)innerRow * KDIM + innerCol;
    const float* Wptr = W + (size_t)cCol * BN * KDIM + (size_t)innerRow * KDIM + innerCol;

    u64 acc2[TM * TN / 2];                 // pairs along N: 32 u64 = 64 regs
    #pragma unroll
    for (int i = 0; i < TM * TN / 2; i++) acc2[i] = 0ull;

    // ---- stage tile 0 ----
    float4 ra = *reinterpret_cast<const float4*>(Aptr);
    float4 rb = *reinterpret_cast<const float4*>(Wptr);
    {
        const float av[4] = {ra.x, ra.y, ra.z, ra.w};
        const float bv[4] = {rb.x, rb.y, rb.z, rb.w};
        #pragma unroll
        for (int j = 0; j < 4; j++) {
            As[0][innerCol + j][innerRow] = av[j];
            Bs[0][innerCol + j][innerRow] = bv[j];
        }
    }
    __syncthreads();

    // ---- compute one k-tile from buffer `buf` (k ascending, FFMA2 chains) ----
    auto compute_tile = [&](int buf) {
        #pragma unroll
        for (int k = 0; k < BK; k++) {
            float4 a0 = *reinterpret_cast<const float4*>(&As[buf][k][threadRow + 0]);
            float4 a1 = *reinterpret_cast<const float4*>(&As[buf][k][threadRow + 4]);
            float4 b0 = *reinterpret_cast<const float4*>(&Bs[buf][k][colLo]);  // conflict-free
            float4 b1 = *reinterpret_cast<const float4*>(&Bs[buf][k][colHi]);

            u64 n[4];
            memcpy(&n[0], &b0.x, 8); memcpy(&n[1], &b0.z, 8);
            memcpy(&n[2], &b1.x, 8); memcpy(&n[3], &b1.z, 8);

            const float mv[TM] = {a0.x, a0.y, a0.z, a0.w, a1.x, a1.y, a1.z, a1.w};
            u64 m2[TM];
            #pragma unroll
            for (int i = 0; i < TM; i++) m2[i] = pack2(mv[i], mv[i]);  // ALU pipe

            #pragma unroll
            for (int p = 0; p < 4; p++) {
                #pragma unroll
                for (int i = 0; i < TM; i++) {
                    fma2(acc2[i * 4 + p], m2[i], n[p]);
                }
            }
        }
    };

    // ---- main loop: tiles 0..126  (k = 0..1015, the Eigen kc=1016 panel) ----
    for (int kb = 0; kb < NKB - 1; kb++) {
        const int cur = kb & 1, nxt = cur ^ 1;

        ra = *reinterpret_cast<const float4*>(Aptr + (size_t)(kb + 1) * BK);
        rb = *reinterpret_cast<const float4*>(Wptr + (size_t)(kb + 1) * BK);

        compute_tile(cur);

        const float av[4] = {ra.x, ra.y, ra.z, ra.w};
        const float bv[4] = {rb.x, rb.y, rb.z, rb.w};
        #pragma unroll
        for (int j = 0; j < 4; j++) {
            As[nxt][innerCol + j][innerRow] = av[j];
            Bs[nxt][innerCol + j][innerRow] = bv[j];
        }
        __syncthreads();
    }

    // ---- Eigen fold at k=1016: sum <- chain  (bitwise == fadd(0, chain)) ----
    u64 sum2[TM * TN / 2];
    #pragma unroll
    for (int i = 0; i < TM * TN / 2; i++) { sum2[i] = acc2[i]; acc2[i] = 0ull; }

    // ---- tail tile 127 (k = 1016..1023) ----
    compute_tile((NKB - 1) & 1);

    // ---- epilogue: o = fadd(fadd(sum, tail), bias)  (scalar, exactly R7) ----
    #pragma unroll
    for (int i = 0; i < TM; i++) {
        const size_t row = (size_t)cRow * BM + threadRow + i;
        #pragma unroll
        for (int half = 0; half < 2; half++) {
            const int col = cCol * BN + (half == 0 ? colLo : colHi);
            float4 bv = *reinterpret_cast<const float4*>(&bias[col]);
            float s[4], t[4];
            memcpy(&s[0], &sum2[i * 4 + half * 2 + 0], 8);
            memcpy(&s[2], &sum2[i * 4 + half * 2 + 1], 8);
            memcpy(&t[0], &acc2[i * 4 + half * 2 + 0], 8);
            memcpy(&t[2], &acc2[i * 4 + half * 2 + 1], 8);
            float4 o;
            o.x = __fadd_rn(__fadd_rn(s[0], t[0]), bv.x);
            o.y = __fadd_rn(__fadd_rn(s[1], t[1]), bv.y);
            o.z = __fadd_rn(__fadd_rn(s[2], t[2]), bv.z);
            o.w = __fadd_rn(__fadd_rn(s[3], t[3]), bv.w);
            *reinterpret_cast<float4*>(&g_I[row * HDIM + col]) = o;
        }
    }

    // ---- release: this CTA's slice of batch cRow/4 is globally visible ----
    __threadfence();
    __syncthreads();
    if (tid == 0) atomicAdd(&g_ready[cRow >> 2], 1u);
}

// ---------------------------------------------------------------------------
// Flag reset — head of every captured sequence (replay-deterministic).
// ---------------------------------------------------------------------------
__global__ void zero_flags() {
    if (threadIdx.x < BDIM) g_ready[threadIdx.x] = 0u;
}

// ---------------------------------------------------------------------------
// LIF scan v3: launched CONCURRENTLY with the GEMM. Each CTA covers 128
// (b,h) pairs of a single batch; it spin-waits (nanosleep backoff) until all
// 32 GEMM CTAs of that batch have released, then runs the R14 chunked-
// prefetch body (arithmetic bitwise-identical to R7/R14).
// 128 threads/CTA keeps the CTA tiny (~3.8K regs) so it co-resides with
// GEMM CTAs — guarantees forward progress (no deadlock).
// ---------------------------------------------------------------------------
constexpr int SCHUNK = 16;

__global__ __launch_bounds__(128) void lif_scan(
    float* __restrict__ spikes,      // [B,T,H]
    float* __restrict__ mem_final)   // [B,H]
{
    const int idx = blockIdx.x * 128 + threadIdx.x;   // over B*H
    const int b = idx / HDIM;
    const int h = idx % HDIM;

    // wait until batch b's GEMM output is complete (32 producer CTAs)
    if (threadIdx.x == 0) {
        while (atomicAdd(&g_ready[b], 0u) < 32u) __nanosleep(256);
    }
    __syncthreads();
    __threadfence();   // acquire: order g_I loads after the observed release

    const float* Ip = g_I + (size_t)b * TDIM * HDIM + h;
    float* Sp = spikes + (size_t)b * TDIM * HDIM + h;

    float mem = 0.0f;
    for (int tb = 0; tb < TDIM; tb += SCHUNK) {
        float v[SCHUNK];
        #pragma unroll
        for (int j = 0; j < SCHUNK; j++)
            v[j] = Ip[(size_t)(tb + j) * HDIM];          // independent LDGs

        #pragma unroll
        for (int j = 0; j < SCHUNK; j++) {
            mem = __fadd_rn(__fmul_rn(ALPHA, mem), v[j]);
            const bool fire = (mem >= 1.0f);
            Sp[(size_t)(tb + j) * HDIM] = fire ? 1.0f : 0.0f;
            mem = fire ? 0.0f : mem;
        }
    }
    mem_final[idx] = mem;
}

// ---------------------------------------------------------------------------
// Overlap resources (host/driver objects only — created at static init).
// NonBlocking is REQUIRED so the side stream doesn't serialize against the
// legacy capture stream.
// ---------------------------------------------------------------------------
static cudaStream_t g_s1;
static cudaEvent_t  g_evFork, g_evJoin;
static struct StreamInit {
    StreamInit() {
        cudaStreamCreateWithFlags(&g_s1, cudaStreamNonBlocking);
        cudaEventCreateWithFlags(&g_evFork, cudaEventDisableTiming);
        cudaEventCreateWithFlags(&g_evJoin, cudaEventDisableTiming);
    }
} g_streamInit;

extern "C" void kernel_launch(void* const* d_in, const int* in_sizes, int n_in,
                              void* d_out, int out_size)
{
    const float* x  = (const float*)d_in[0];   // [B,T,IN]
    const float* W  = (const float*)d_in[1];   // [HID,IN]
    const float* b  = (const float*)d_in[2];   // [HID]

    float* out      = (float*)d_out;
    float* spikes   = out;                                   // B*T*H floats
    float* mem_fin  = out + (size_t)MTOT * HDIM;             // B*H floats

    // 1) reset per-batch flags (main stream), fork point for the scan stream
    zero_flags<<<1, 64>>>();
    cudaEventRecord(g_evFork, 0);

    // 2) full GEMM (single kernel, 14 clean waves) on the main stream
    sgemm_nt_bias_eigen_f32x2<<<dim3(HDIM / BN, MTOT / BM), 256>>>(x, W, b);

    // 3) scan runs CONCURRENTLY on the side stream, gated per-batch by flags
    cudaStreamWaitEvent(g_s1, g_evFork, 0);
    lif_scan<<<(BDIM * HDIM) / 128, 128, 0, g_s1>>>(spikes, mem_fin);
    cudaEventRecord(g_evJoin, g_s1);

    // 4) join the side stream back into the main stream
    cudaStreamWaitEvent(0, g_evJoin, 0);
}